// round 6
// baseline (speedup 1.0000x reference)
#include <cuda_runtime.h>
#include <cuda_fp16.h>
#include <cstdint>

#define SPX 3136      // 56*56
#define BATCH 8
#define DIM 256
#define DIM2 512
#define ROWS_TOT (BATCH * SPX)   // 25088 = 196 * 128

// ---------------- scratch (static __device__, allocation-free) ----------------
__device__ __half g_xTh[(size_t)ROWS_TOT * DIM];     // fp16(x^T) [B*S, 256]
__device__ __half g_cath[(size_t)ROWS_TOT * DIM2];   // [B*S, 512] = [h | xj]
__device__ __half g_gh[(size_t)ROWS_TOT * DIM2];     // gelu out [B*S, 512]
__device__ __half g_w1h[(size_t)DIM * DIM];          // fp16(w1) [256,256]
__device__ __half g_wgh[(size_t)DIM2 * DIM2];        // fp16(wg) [512,512]
__device__ __half g_w2h[(size_t)DIM * DIM2];         // fp16(w2) [256,512]
__device__ float g_cm1[(size_t)BATCH * 56 * 2 * DIM], g_cm2[(size_t)BATCH * 56 * 2 * DIM];
__device__ float g_sc1[DIM], g_sh1[DIM];
__device__ float g_scg[DIM2], g_shg[DIM2];
__device__ float g_sc2[DIM], g_sh2[DIM];

// ---------------- PTX helpers (sm_80-generic only) ----------------
__device__ __forceinline__ uint32_t smem_u32(const void* p) {
    uint32_t a;
    asm("{ .reg .u64 t; cvta.to.shared.u64 t, %1; cvt.u32.u64 %0, t; }" : "=r"(a) : "l"(p));
    return a;
}
#define CP_ASYNC16(sm, gm) \
    asm volatile("cp.async.cg.shared.global [%0], [%1], 16;" :: "r"(sm), "l"(gm) : "memory")
#define CP_COMMIT() asm volatile("cp.async.commit_group;" ::: "memory")
#define CP_WAIT1() asm volatile("cp.async.wait_group 1;" ::: "memory")
#define CP_WAIT0() asm volatile("cp.async.wait_group 0;" ::: "memory")
#define LDSM_X4(r0, r1, r2, r3, addr)                                        \
    asm volatile("ldmatrix.sync.aligned.m8n8.x4.shared.b16 {%0,%1,%2,%3}, [%4];" \
                 : "=r"(r0), "=r"(r1), "=r"(r2), "=r"(r3) : "r"(addr))

__device__ __forceinline__ void mma_fp16(float* d, const uint32_t* a, const uint32_t* b) {
    asm volatile(
        "mma.sync.aligned.m16n8k16.row.col.f32.f16.f16.f32 "
        "{%0,%1,%2,%3}, {%4,%5,%6,%7}, {%8,%9}, {%0,%1,%2,%3};"
        : "+f"(d[0]), "+f"(d[1]), "+f"(d[2]), "+f"(d[3])
        : "r"(a[0]), "r"(a[1]), "r"(a[2]), "r"(a[3]), "r"(b[0]), "r"(b[1]));
}

// two-smallest update / merge (exact exclude-self min machinery)
__device__ __forceinline__ void ts_upd(float& m1, float& m2, float v) {
    if (v < m1) { m2 = m1; m1 = v; } else if (v < m2) { m2 = v; }
}
__device__ __forceinline__ void ts_merge(float a1, float a2, float b1, float b2,
                                         float& r1, float& r2) {
    r1 = fminf(a1, b1);
    r2 = fminf(fmaxf(a1, b1), fminf(a2, b2));
}

// ---------------- fused prep + weight packing ----------------
__global__ void prep_pack(const float* __restrict__ w1, const float* __restrict__ wg,
                          const float* __restrict__ w2,
                          const float* __restrict__ b1, const float* __restrict__ g1,
                          const float* __restrict__ be1, const float* __restrict__ m1,
                          const float* __restrict__ v1,
                          const float* __restrict__ bg, const float* __restrict__ gg,
                          const float* __restrict__ beg, const float* __restrict__ mg,
                          const float* __restrict__ vg,
                          const float* __restrict__ b2, const float* __restrict__ g2,
                          const float* __restrict__ be2, const float* __restrict__ m2,
                          const float* __restrict__ v2) {
    int blk = blockIdx.x;
    if (blk < 1792) {
        int idx = blk * 256 + threadIdx.x;
        if (idx < 65536) {
            g_w1h[idx] = __float2half_rn(w1[idx]);
        } else if (idx < 65536 + 262144) {
            int j = idx - 65536;
            g_wgh[j] = __float2half_rn(wg[j]);
        } else {
            int j = idx - 65536 - 262144;
            g_w2h[j] = __float2half_rn(w2[j]);
        }
        return;
    }
    int i = threadIdx.x;
    {
        float s = g1[i] / sqrtf(v1[i] + 1e-5f);
        g_sc1[i] = s; g_sh1[i] = (b1[i] - m1[i]) * s + be1[i];
        float s2 = g2[i] / sqrtf(v2[i] + 1e-5f);
        g_sc2[i] = s2; g_sh2[i] = (b2[i] - m2[i]) * s2 + be2[i];
    }
#pragma unroll
    for (int r = 0; r < 2; r++) {
        int j = i + r * 256;
        float sg = gg[j] / sqrtf(vg[j] + 1e-5f);
        g_scg[j] = sg; g_shg[j] = (bg[j] - mg[j]) * sg + beg[j];
    }
}

// ---------------- transpose x [B,256,S] -> fp16 [B*S, 256] ----------------
__global__ void __launch_bounds__(256) transpose_in_pack(const float* __restrict__ x) {
    __shared__ float t[32][33];
    int tx = threadIdx.x & 31, ty = threadIdx.x >> 5;
    int s0 = blockIdx.x * 32, c0 = blockIdx.y * 32, b = blockIdx.z;
    const float* xp = x + ((size_t)b * DIM + c0) * SPX + s0;
    for (int i = ty; i < 32; i += 8) t[i][tx] = xp[(size_t)i * SPX + tx];
    __syncthreads();
    __half* op = g_xTh + ((size_t)(b * SPX + s0)) * DIM + c0;
    for (int i = ty; i < 32; i += 8)
        op[(size_t)i * DIM + tx] = __float2half_rn(t[tx][i]);
}

// ---------------- MRConv4d: column pass (two-smallest per (x, y-parity)) ----------------
// 128 threads: each handles channel pair (2c2, 2c2+1). 4 mod-4 trackers for MLP.
__global__ void __launch_bounds__(128) colmin_kernel() {
    int x = blockIdx.x, b = blockIdx.y, c2 = threadIdx.x;
    const __half2* base = (const __half2*)(g_cath + ((size_t)b * SPX) * DIM2) + c2;
    float2 m1[4], m2[4];
#pragma unroll
    for (int q = 0; q < 4; q++) {
        m1[q] = make_float2(1e30f, 1e30f);
        m2[q] = make_float2(1e30f, 1e30f);
    }
    for (int y4 = 0; y4 < 14; y4++) {
#pragma unroll
        for (int q = 0; q < 4; q++) {
            int y = y4 * 4 + q;
            __half2 hv = __ldg((const __half2*)&base[(size_t)(y * 56 + x) * 256]);
            float2 v = __half22float2(hv);
            ts_upd(m1[q].x, m2[q].x, v.x);
            ts_upd(m1[q].y, m2[q].y, v.y);
        }
    }
    float2 e1, e2, o1, o2;
    ts_merge(m1[0].x, m2[0].x, m1[2].x, m2[2].x, e1.x, e2.x);
    ts_merge(m1[0].y, m2[0].y, m1[2].y, m2[2].y, e1.y, e2.y);
    ts_merge(m1[1].x, m2[1].x, m1[3].x, m2[3].x, o1.x, o2.x);
    ts_merge(m1[1].y, m2[1].y, m1[3].y, m2[3].y, o1.y, o2.y);
    size_t o = ((size_t)(b * 56 + x) * 2) * DIM + 2 * c2;
    *(float2*)&g_cm1[o] = e1;
    *(float2*)&g_cm2[o] = e2;
    *(float2*)&g_cm1[o + DIM] = o1;
    *(float2*)&g_cm2[o + DIM] = o2;
}

// ---------------- MRConv4d: row pass + combine -> xj ----------------
__global__ void __launch_bounds__(128) row_combine_kernel() {
    int y = blockIdx.x, b = blockIdx.y, c2 = threadIdx.x;
    const __half2* base = (const __half2*)(g_cath + ((size_t)(b * SPX + y * 56)) * DIM2) + c2;
    __half2 hv[56];
    float2 m1[4], m2[4];
#pragma unroll
    for (int q = 0; q < 4; q++) {
        m1[q] = make_float2(1e30f, 1e30f);
        m2[q] = make_float2(1e30f, 1e30f);
    }
    for (int x4 = 0; x4 < 14; x4++) {
#pragma unroll
        for (int q = 0; q < 4; q++) {
            int x = x4 * 4 + q;
            hv[x] = __ldg((const __half2*)&base[(size_t)x * 256]);
            float2 v = __half22float2(hv[x]);
            ts_upd(m1[q].x, m2[q].x, v.x);
            ts_upd(m1[q].y, m2[q].y, v.y);
        }
    }
    float2 e1, e2, o1, o2;
    ts_merge(m1[0].x, m2[0].x, m1[2].x, m2[2].x, e1.x, e2.x);
    ts_merge(m1[0].y, m2[0].y, m1[2].y, m2[2].y, e1.y, e2.y);
    ts_merge(m1[1].x, m2[1].x, m1[3].x, m2[3].x, o1.x, o2.x);
    ts_merge(m1[1].y, m2[1].y, m1[3].y, m2[3].y, o1.y, o2.y);

    int py = y & 1;
    __half2* ob = (__half2*)(g_cath + ((size_t)(b * SPX + y * 56)) * DIM2 + DIM) + c2;
    const size_t cmb = ((size_t)(b * 56) * 2 + py) * DIM + 2 * c2;
    for (int x = 0; x < 56; x++) {
        float2 v = __half22float2(hv[x]);
        size_t o = cmb + (size_t)x * 2 * DIM;
        float2 c1 = *(const float2*)&g_cm1[o];
        float2 cc2 = *(const float2*)&g_cm2[o];
        float ecx = (v.x == c1.x) ? cc2.x : c1.x;
        float ecy = (v.y == c1.y) ? cc2.y : c1.y;
        float2 r1 = (x & 1) ? o1 : e1;
        float2 r2 = (x & 1) ? o2 : e2;
        float erx = (v.x == r1.x) ? r2.x : r1.x;
        float ery = (v.y == r1.y) ? r2.y : r1.y;
        float jx = fmaxf(0.0f, v.x - fminf(ecx, erx));
        float jy = fmaxf(0.0f, v.y - fminf(ecy, ery));
        ob[(size_t)x * 256] = __floats2half2_rn(jx, jy);
    }
}

// ---------------- fp16 mma.sync GEMM: CTA 128x256, warp 64x64, BK=64 ----------------
// D[r,n] = sum_k A[r0+r,k] * W[n0+n,k]
// 8 warps (2m x 4n), 1 CTA/SM, double-buffered cp.async.
// MODE 0: BN -> fp16, row stride 512 (fc1)
// MODE 1: BN + exact GELU -> fp16, row stride 512 (gemm2)
// MODE 2: BN + residual -> transposed fp32 out[B,256,S] via 2x staged 128-col transpose
#define GSMEM 98304
template <int MODE>
__global__ void __launch_bounds__(256, 1)
fp16_gemm(const __half* __restrict__ Ag, const __half* __restrict__ Wg,
          void* __restrict__ dstv, const float* __restrict__ xres,
          const float* __restrict__ scale, const float* __restrict__ shift, int K) {
    extern __shared__ __align__(1024) char smem[];
    __shared__ float s_scale[256], s_shift[256];
    const int tid = threadIdx.x, lane = tid & 31, wid = tid >> 5;
    const int warp_m = wid >> 2, warp_n = wid & 3;
    const int r0 = blockIdx.x * 128, n0 = blockIdx.y * 256;
    const uint32_t sb = smem_u32(smem);
    s_scale[tid] = scale[n0 + tid];
    s_shift[tid] = shift[n0 + tid];

    // loader bases (affine in i)
    const int lrow = tid >> 3, lc = tid & 7;
    const uint32_t lsw = lrow * 128 + ((lc ^ (lrow & 7)) << 4);
    const size_t aoffs = (size_t)(r0 + lrow) * K + lc * 8;
    const size_t boffs = (size_t)(n0 + lrow) * K + lc * 8;

    // ldmatrix bases
    const int rA = (lane & 7) + ((lane >> 3) & 1) * 8;
    const int kcA = lane >> 4;
    const int rB = (lane & 7) + ((lane >> 4) & 1) * 8;
    const int kcB = (lane >> 3) & 1;

    float acc[4][8][4];
#pragma unroll
    for (int a = 0; a < 4; a++)
#pragma unroll
        for (int b = 0; b < 8; b++)
#pragma unroll
            for (int i = 0; i < 4; i++) acc[a][b][i] = 0.0f;

    const int NS = K >> 6;

    // prologue: stage 0 -> buf 0 (A at +0 [16KB], B at +16384 [32KB], stage stride 49152)
#pragma unroll
    for (int i = 0; i < 4; i++)
        CP_ASYNC16(sb + lsw + i * 4096, Ag + aoffs + (size_t)i * 32 * K);
#pragma unroll
    for (int i = 0; i < 8; i++)
        CP_ASYNC16(sb + 16384 + lsw + i * 4096, Wg + boffs + (size_t)i * 32 * K);
    CP_COMMIT();

    for (int s = 0; s < NS; s++) {
        const int buf = s & 1;
        if (s + 1 < NS) {
            const uint32_t nb = sb + (buf ^ 1) * 49152;
            const size_t kadd = (size_t)(s + 1) * 64;
#pragma unroll
            for (int i = 0; i < 4; i++)
                CP_ASYNC16(nb + lsw + i * 4096, Ag + aoffs + (size_t)i * 32 * K + kadd);
#pragma unroll
            for (int i = 0; i < 8; i++)
                CP_ASYNC16(nb + 16384 + lsw + i * 4096, Wg + boffs + (size_t)i * 32 * K + kadd);
            CP_COMMIT();
            CP_WAIT1();
        } else {
            CP_WAIT0();
        }
        __syncthreads();

        const uint32_t aBase = sb + buf * 49152;
        const uint32_t bBase = aBase + 16384;
#pragma unroll
        for (int kk = 0; kk < 4; kk++) {
            uint32_t af[4][4];
#pragma unroll
            for (int mf = 0; mf < 4; mf++) {
                int row = warp_m * 64 + mf * 16 + rA;
                uint32_t addr = aBase + row * 128 + (((kk * 2 + kcA) ^ (row & 7)) << 4);
                LDSM_X4(af[mf][0], af[mf][1], af[mf][2], af[mf][3], addr);
            }
            uint32_t bf[4][4];
#pragma unroll
            for (int nb2 = 0; nb2 < 4; nb2++) {
                int row = warp_n * 64 + nb2 * 16 + rB;
                uint32_t addr = bBase + row * 128 + (((kk * 2 + kcB) ^ (row & 7)) << 4);
                LDSM_X4(bf[nb2][0], bf[nb2][1], bf[nb2][2], bf[nb2][3], addr);
            }
#pragma unroll
            for (int mf = 0; mf < 4; mf++)
#pragma unroll
                for (int nf = 0; nf < 8; nf++)
                    mma_fp16(acc[mf][nf], af[mf], &bf[nf >> 1][(nf & 1) * 2]);
        }
        __syncthreads();
    }

    // ---------------- epilogue ----------------
    if (MODE == 2) {
        float* stg = (float*)smem;  // 128 x 129 fp32 staging (66 KB < 96 KB)
        float* out = (float*)dstv;
#pragma unroll
        for (int h2 = 0; h2 < 2; h2++) {
            if ((warp_n >> 1) == h2) {
#pragma unroll
                for (int mf = 0; mf < 4; mf++)
#pragma unroll
                    for (int nf = 0; nf < 8; nf++)
#pragma unroll
                        for (int half = 0; half < 2; half++) {
                            int rl = warp_m * 64 + mf * 16 + (lane >> 2) + half * 8;
                            int cl = (warp_n & 1) * 64 + nf * 8 + (lane & 3) * 2;
                            int cg = h2 * 128 + cl;
                            stg[rl * 129 + cl] =
                                fmaf(acc[mf][nf][half * 2 + 0], s_scale[cg], s_shift[cg]);
                            stg[rl * 129 + cl + 1] =
                                fmaf(acc[mf][nf][half * 2 + 1], s_scale[cg + 1], s_shift[cg + 1]);
                        }
            }
            __syncthreads();
#pragma unroll
            for (int cc = 0; cc < 16; cc++) {
                int c = wid * 16 + cc;
#pragma unroll
                for (int j = 0; j < 4; j++) {
                    int i = lane + 32 * j;
                    int r = r0 + i;
                    int b = r / SPX;
                    size_t o = ((size_t)(b * DIM + h2 * 128 + c)) * SPX + (r - b * SPX);
                    out[o] = stg[i * 129 + c] + xres[o];
                }
            }
            __syncthreads();
        }
        return;
    }

    const int mw = r0 + warp_m * 64;
    const int nw = warp_n * 64;
    __half* dp_base = (__half*)dstv;
#pragma unroll
    for (int mf = 0; mf < 4; mf++) {
#pragma unroll
        for (int nf = 0; nf < 8; nf++) {
#pragma unroll
            for (int half = 0; half < 2; half++) {
                int grow = mw + mf * 16 + (lane >> 2) + half * 8;
                int lcol = nw + nf * 8 + (lane & 3) * 2;
                float v0 = fmaf(acc[mf][nf][half * 2 + 0], s_scale[lcol], s_shift[lcol]);
                float v1 = fmaf(acc[mf][nf][half * 2 + 1], s_scale[lcol + 1], s_shift[lcol + 1]);
                if (MODE == 1) {
                    v0 = 0.5f * v0 * (1.0f + erff(v0 * 0.70710678118654752f));
                    v1 = 0.5f * v1 * (1.0f + erff(v1 * 0.70710678118654752f));
                }
                __half2 hp;
                hp.x = __float2half_rn(v0);
                hp.y = __float2half_rn(v1);
                *(__half2*)(dp_base + (size_t)grow * DIM2 + n0 + lcol) = hp;
            }
        }
    }
}

// ---------------------------------------------------------------------------
extern "C" void kernel_launch(void* const* d_in, const int* in_sizes, int n_in,
                              void* d_out, int out_size) {
    const float* x   = (const float*)d_in[0];
    const float* w1  = (const float*)d_in[1];
    const float* b1  = (const float*)d_in[2];
    const float* g1  = (const float*)d_in[3];
    const float* be1 = (const float*)d_in[4];
    const float* m1  = (const float*)d_in[5];
    const float* v1  = (const float*)d_in[6];
    const float* wg  = (const float*)d_in[7];
    const float* bg  = (const float*)d_in[8];
    const float* gg  = (const float*)d_in[9];
    const float* beg = (const float*)d_in[10];
    const float* mg  = (const float*)d_in[11];
    const float* vg  = (const float*)d_in[12];
    const float* w2  = (const float*)d_in[13];
    const float* b2  = (const float*)d_in[14];
    const float* g2  = (const float*)d_in[15];
    const float* be2 = (const float*)d_in[16];
    const float* m2  = (const float*)d_in[17];
    const float* v2  = (const float*)d_in[18];

    __half *xTh, *cath, *gh, *w1h, *wgh, *w2h;
    float *sc1, *sh1, *scg, *shg, *sc2, *sh2;
    cudaGetSymbolAddress((void**)&xTh, g_xTh);
    cudaGetSymbolAddress((void**)&cath, g_cath);
    cudaGetSymbolAddress((void**)&gh, g_gh);
    cudaGetSymbolAddress((void**)&w1h, g_w1h);
    cudaGetSymbolAddress((void**)&wgh, g_wgh);
    cudaGetSymbolAddress((void**)&w2h, g_w2h);
    cudaGetSymbolAddress((void**)&sc1, g_sc1);
    cudaGetSymbolAddress((void**)&sh1, g_sh1);
    cudaGetSymbolAddress((void**)&scg, g_scg);
    cudaGetSymbolAddress((void**)&shg, g_shg);
    cudaGetSymbolAddress((void**)&sc2, g_sc2);
    cudaGetSymbolAddress((void**)&sh2, g_sh2);

    cudaFuncSetAttribute(fp16_gemm<0>, cudaFuncAttributeMaxDynamicSharedMemorySize, GSMEM);
    cudaFuncSetAttribute(fp16_gemm<1>, cudaFuncAttributeMaxDynamicSharedMemorySize, GSMEM);
    cudaFuncSetAttribute(fp16_gemm<2>, cudaFuncAttributeMaxDynamicSharedMemorySize, GSMEM);

    prep_pack<<<1793, 256>>>(w1, wg, w2, b1, g1, be1, m1, v1,
                             bg, gg, beg, mg, vg, b2, g2, be2, m2, v2);
    transpose_in_pack<<<dim3(98, 8, 8), 256>>>(x);

    // fc1: cat[:, 0:256] = fp16(BN(x @ w1^T))   (N = 256 -> one N tile)
    fp16_gemm<0><<<dim3(196, 1), 256, GSMEM>>>(xTh, w1h, cath, nullptr, sc1, sh1, DIM);
    // MRConv4d -> cat[:, 256:512]
    colmin_kernel<<<dim3(56, 8), 128>>>();
    row_combine_kernel<<<dim3(56, 8), 128>>>();
    // g = fp16(GELU(BN(cat @ wg^T)))            (N = 512 -> two N tiles)
    fp16_gemm<1><<<dim3(196, 2), 256, GSMEM>>>(cath, wgh, gh, nullptr, scg, shg, DIM2);
    // out[B,256,S] = BN(g @ w2^T)^T + x         (fused transpose + residual)
    fp16_gemm<2><<<dim3(196, 1), 256, GSMEM>>>(gh, w2h, d_out, x, sc2, sh2, DIM2);
}